// round 17
// baseline (speedup 1.0000x reference)
#include <cuda_runtime.h>
#include <cuda_fp16.h>
#include <stdint.h>
#include <math.h>

#define NN 2000
#define EE 16000
#define BB 16
#define LL 256
#define HH 2000
#define FIN 100
#define GG 200

// ---------------- scratch ----------------
__device__ float g_h[(size_t)NN * HH];
__device__ float g_te[(size_t)NN * 4000];
__device__ float g_gh[(size_t)NN * 6000];
__device__ float g_gi[(size_t)NN * 6000];
__device__ int   g_off[NN + 1];
__device__ int   g_cnt[NN];
__device__ int   g_csr[EE];
__device__ int   g_boff[BB + 1];
__device__ float g_gt[(size_t)LL * BB * 1200];
__device__ float g_f1[BB * 1000];
__device__ float g_f2[BB * 500];

__device__ __half g_hh[(size_t)2000 * 2048], g_hl[(size_t)2000 * 2048];
__device__ __half g_ah[(size_t)2000 * 2048], g_al[(size_t)2000 * 2048];
__device__ __half g_Wch[(size_t)10000 * 2048];
__device__ __half g_Wihh[(size_t)6000 * 2048];
__device__ __half g_gWh[(size_t)3600 * 448];
__device__ __half g_l1h[(size_t)1000 * 3200];
__device__ __half g_l11h[(size_t)500 * 1024];
__device__ __half g_WTh[3 * 2 * 200 * 600];
__device__ __half g_xh[(size_t)4096 * 448], g_xl[(size_t)4096 * 448];
__device__ __half g_x2h[(size_t)4096 * 448], g_x2l[(size_t)4096 * 448];
__device__ __half g_ch[(size_t)16 * 3200], g_cl[(size_t)16 * 3200];
__device__ __half g_f1h[(size_t)16 * 1024], g_f1l[(size_t)16 * 1024];

// ---------------- helpers ----------------
__device__ __forceinline__ float sigm(float x) { return 1.f / (1.f + expf(-x)); }
__device__ __forceinline__ void splitw(float v, __half& h, __half& l) {
    h = __float2half_rn(v);
    l = __float2half_rn(v - __half2float(h));
}
__device__ __forceinline__ uint32_t s2u(const void* p) {
    uint32_t a;
    asm("{ .reg .u64 t; cvta.to.shared.u64 t, %1; cvt.u32.u64 %0, t; }" : "=r"(a) : "l"(p));
    return a;
}
__device__ __forceinline__ void cpa16(uint32_t dst, const void* src, uint32_t sz) {
    asm volatile("cp.async.ca.shared.global [%0], [%1], 16, %2;" :: "r"(dst), "l"(src), "r"(sz));
}
__device__ __forceinline__ void ldm4(uint32_t* r, uint32_t addr) {
    asm volatile("ldmatrix.sync.aligned.m8n8.x4.shared.b16 {%0,%1,%2,%3}, [%4];"
                 : "=r"(r[0]), "=r"(r[1]), "=r"(r[2]), "=r"(r[3]) : "r"(addr));
}
__device__ __forceinline__ void hmma(float* c, const uint32_t* a, const uint32_t* b) {
    asm volatile("mma.sync.aligned.m16n8k16.row.col.f32.f16.f16.f32 "
                 "{%0,%1,%2,%3},{%4,%5,%6,%7},{%8,%9},{%0,%1,%2,%3};"
                 : "+f"(c[0]), "+f"(c[1]), "+f"(c[2]), "+f"(c[3])
                 : "r"(a[0]), "r"(a[1]), "r"(a[2]), "r"(a[3]), "r"(b[0]), "r"(b[1]));
}

// ============ 2-term GEMM (token/head): C = act((Ah+Al) @ Bh^T + bias) ========
#define RS 144
#define MATAB (128 * RS)
#define MATBB (64 * RS)
#define BUFB (2 * MATAB + MATBB)
#define SMEM_DYN (2 * BUFB)

__global__ __launch_bounds__(256, 2) void hgemm(
    const __half* __restrict__ Ah, const __half* __restrict__ Al, int ldA,
    const __half* __restrict__ Bh, int ldB,
    const float* __restrict__ bias, float* __restrict__ C, int ldc,
    int M, int N, int K, int act)
{
    extern __shared__ char smem[];
    const uint32_t sb = s2u(smem);
    const int tid = threadIdx.x;
    const int warp = tid >> 5, lane = tid & 31;
    const int wm = warp & 3, wn = warp >> 2;
    const int br = blockIdx.y * 128, bc = blockIdx.x * 64;
    const int nk = K >> 6;

    float acc[2][4][4];
#pragma unroll
    for (int mt = 0; mt < 2; mt++)
#pragma unroll
        for (int nt = 0; nt < 4; nt++)
#pragma unroll
            for (int r = 0; r < 4; r++) acc[mt][nt][r] = 0.f;

    auto issue = [&](int c) {
        uint32_t tb = sb + (uint32_t)(c & 1) * BUFB;
        int k0 = c << 6;
#pragma unroll
        for (int i = 0; i < 10; i++) {
            int g = (i << 8) + tid;
            if (g < 2048) {
                int which = g >> 10;
                int row = (g >> 3) & 127;
                int kb = g & 7;
                uint32_t dst = tb + which * MATAB + row * RS + kb * 16;
                int gr = br + row;
                const __half* base = which ? Al : Ah;
                uint32_t sz = (gr < M) ? 16u : 0u;
                cpa16(dst, base + (size_t)(gr < M ? gr : 0) * ldA + k0 + kb * 8, sz);
            } else {
                int g2 = g - 2048;
                int row = g2 >> 3;
                int kb = g2 & 7;
                uint32_t dst = tb + 2 * MATAB + row * RS + kb * 16;
                int gn = bc + row;
                uint32_t sz = (gn < N) ? 16u : 0u;
                cpa16(dst, Bh + (size_t)(gn < N ? gn : 0) * ldB + k0 + kb * 8, sz);
            }
        }
        asm volatile("cp.async.commit_group;");
    };

    const int arow = wm * 32 + (lane & 15);
    const int ak = (lane >> 4);
    const int brow = wn * 32 + (lane & 7) + ((lane >> 4) << 3);
    const int bk = ((lane >> 3) & 1);

    auto compute = [&](int c) {
        uint32_t tb = sb + (uint32_t)(c & 1) * BUFB;
        uint32_t aAh = tb, aAl = tb + MATAB, aBh = tb + 2 * MATAB;
#pragma unroll
        for (int k16 = 0; k16 < 4; k16++) {
            uint32_t ah[2][4], al[2][4];
#pragma unroll
            for (int mt = 0; mt < 2; mt++) {
                uint32_t off = (uint32_t)(arow + mt * 16) * RS + (2 * k16 + ak) * 16;
                ldm4(ah[mt], aAh + off);
                ldm4(al[mt], aAl + off);
            }
            uint32_t bh[4][2];
#pragma unroll
            for (int np = 0; np < 2; np++) {
                uint32_t off = (uint32_t)(brow + np * 16) * RS + (2 * k16 + bk) * 16;
                uint32_t t4[4];
                ldm4(t4, aBh + off);
                bh[np * 2][0] = t4[0]; bh[np * 2][1] = t4[1];
                bh[np * 2 + 1][0] = t4[2]; bh[np * 2 + 1][1] = t4[3];
            }
#pragma unroll
            for (int mt = 0; mt < 2; mt++)
#pragma unroll
                for (int nt = 0; nt < 4; nt++) {
                    hmma(acc[mt][nt], ah[mt], bh[nt]);
                    hmma(acc[mt][nt], al[mt], bh[nt]);
                }
        }
    };

    issue(0);
    for (int c = 0; c < nk; c++) {
        if (c + 1 < nk) {
            issue(c + 1);
            asm volatile("cp.async.wait_group 1;" ::: "memory");
        } else {
            asm volatile("cp.async.wait_group 0;" ::: "memory");
        }
        __syncthreads();
        compute(c);
        __syncthreads();
    }

#pragma unroll
    for (int mt = 0; mt < 2; mt++) {
        int row0 = br + wm * 32 + mt * 16 + (lane >> 2);
#pragma unroll
        for (int nt = 0; nt < 4; nt++) {
            int col = bc + wn * 32 + nt * 8 + ((lane & 3) << 1);
            if (col < N) {
                float b0 = bias ? bias[col] : 0.f;
                float b1 = bias ? bias[col + 1] : 0.f;
#pragma unroll
                for (int hi = 0; hi < 2; hi++) {
                    int row = row0 + hi * 8;
                    if (row < M) {
                        float2 v;
                        v.x = acc[mt][nt][hi * 2] + b0;
                        v.y = acc[mt][nt][hi * 2 + 1] + b1;
                        if (act) { v.x = fmaxf(v.x, 0.f); v.y = fmaxf(v.y, 0.f); }
                        *reinterpret_cast<float2*>(C + (size_t)row * ldc + col) = v;
                    }
                }
            }
        }
    }
}

// ============ 1-term GEMM (GGNN): K-chunk 128, C = act(Ah @ Bh^T + bias) ======
#define RS1 272
#define MATA1 (128 * RS1)
#define MATB1 (64 * RS1)
#define BUF1 (MATA1 + MATB1)
#define SMEM_DYN1 (2 * BUF1)   // 104448

__global__ __launch_bounds__(256, 2) void hgemm1(
    const __half* __restrict__ Ah, int ldA,
    const __half* __restrict__ Bh, int ldB,
    const float* __restrict__ bias, float* __restrict__ C, int ldc,
    int M, int N, int K, int act)
{
    extern __shared__ char smem[];
    const uint32_t sb = s2u(smem);
    const int tid = threadIdx.x;
    const int warp = tid >> 5, lane = tid & 31;
    const int wm = warp & 3, wn = warp >> 2;
    const int br = blockIdx.y * 128, bc = blockIdx.x * 64;
    const int nk = K >> 7;

    float acc[2][4][4];
#pragma unroll
    for (int mt = 0; mt < 2; mt++)
#pragma unroll
        for (int nt = 0; nt < 4; nt++)
#pragma unroll
            for (int r = 0; r < 4; r++) acc[mt][nt][r] = 0.f;

    auto issue = [&](int c) {
        uint32_t tb = sb + (uint32_t)(c & 1) * BUF1;
        int k0 = c << 7;
#pragma unroll
        for (int i = 0; i < 12; i++) {
            int g = (i << 8) + tid;           // 0..3071
            if (g < 2048) {
                int row = g >> 4;             // 0..127
                int kb = g & 15;
                uint32_t dst = tb + row * RS1 + kb * 16;
                int gr = br + row;
                uint32_t sz = (gr < M) ? 16u : 0u;
                cpa16(dst, Ah + (size_t)(gr < M ? gr : 0) * ldA + k0 + kb * 8, sz);
            } else {
                int g2 = g - 2048;            // 0..1023
                int row = g2 >> 4;            // 0..63
                int kb = g2 & 15;
                uint32_t dst = tb + MATA1 + row * RS1 + kb * 16;
                int gn = bc + row;
                uint32_t sz = (gn < N) ? 16u : 0u;
                cpa16(dst, Bh + (size_t)(gn < N ? gn : 0) * ldB + k0 + kb * 8, sz);
            }
        }
        asm volatile("cp.async.commit_group;");
    };

    const int arow = wm * 32 + (lane & 15);
    const int ak = (lane >> 4);
    const int brow = wn * 32 + (lane & 7) + ((lane >> 4) << 3);
    const int bk = ((lane >> 3) & 1);

    auto compute = [&](int c) {
        uint32_t tb = sb + (uint32_t)(c & 1) * BUF1;
        uint32_t aAh = tb, aBh = tb + MATA1;
#pragma unroll
        for (int k16 = 0; k16 < 8; k16++) {
            uint32_t ah[2][4];
#pragma unroll
            for (int mt = 0; mt < 2; mt++) {
                uint32_t off = (uint32_t)(arow + mt * 16) * RS1 + (2 * k16 + ak) * 16;
                ldm4(ah[mt], aAh + off);
            }
            uint32_t bh[4][2];
#pragma unroll
            for (int np = 0; np < 2; np++) {
                uint32_t off = (uint32_t)(brow + np * 16) * RS1 + (2 * k16 + bk) * 16;
                uint32_t t4[4];
                ldm4(t4, aBh + off);
                bh[np * 2][0] = t4[0]; bh[np * 2][1] = t4[1];
                bh[np * 2 + 1][0] = t4[2]; bh[np * 2 + 1][1] = t4[3];
            }
#pragma unroll
            for (int mt = 0; mt < 2; mt++)
#pragma unroll
                for (int nt = 0; nt < 4; nt++)
                    hmma(acc[mt][nt], ah[mt], bh[nt]);
        }
    };

    issue(0);
    for (int c = 0; c < nk; c++) {
        if (c + 1 < nk) {
            issue(c + 1);
            asm volatile("cp.async.wait_group 1;" ::: "memory");
        } else {
            asm volatile("cp.async.wait_group 0;" ::: "memory");
        }
        __syncthreads();
        compute(c);
        __syncthreads();
    }

#pragma unroll
    for (int mt = 0; mt < 2; mt++) {
        int row0 = br + wm * 32 + mt * 16 + (lane >> 2);
#pragma unroll
        for (int nt = 0; nt < 4; nt++) {
            int col = bc + wn * 32 + nt * 8 + ((lane & 3) << 1);
            if (col < N) {
                float b0 = bias ? bias[col] : 0.f;
                float b1 = bias ? bias[col + 1] : 0.f;
#pragma unroll
                for (int hi = 0; hi < 2; hi++) {
                    int row = row0 + hi * 8;
                    if (row < M) {
                        float2 v;
                        v.x = acc[mt][nt][hi * 2] + b0;
                        v.y = acc[mt][nt][hi * 2 + 1] + b1;
                        if (act) { v.x = fmaxf(v.x, 0.f); v.y = fmaxf(v.y, 0.f); }
                        *reinterpret_cast<float2*>(C + (size_t)row * ldc + col) = v;
                    }
                }
            }
        }
    }
}

// ---------------- split / convert kernels ----------------
__global__ void k_split(const float* __restrict__ in, __half* __restrict__ oh,
                        __half* __restrict__ ol, int R, int K, int Kp) {
    int idx = blockIdx.x * blockDim.x + threadIdx.x;
    if (idx >= R * Kp) return;
    int r = idx / Kp, c = idx - r * Kp;
    float v = (c < K) ? in[(size_t)r * K + c] : 0.f;
    splitw(v, oh[idx], ol[idx]);
}
__global__ void k_tohalf(const float* __restrict__ in, __half* __restrict__ oh,
                         int R, int K, int Kp) {
    int idx = blockIdx.x * blockDim.x + threadIdx.x;
    if (idx >= R * Kp) return;
    int r = idx / Kp, c = idx - r * Kp;
    float v = (c < K) ? in[(size_t)r * K + c] : 0.f;
    oh[idx] = __float2half_rn(v);
}
__global__ void k_splitfeats(const float* __restrict__ feats, __half* __restrict__ oh,
                             __half* __restrict__ ol) {
    int idx = blockIdx.x * blockDim.x + threadIdx.x;
    if (idx >= 2000 * 2048) return;
    int r = idx >> 11, c = idx & 2047;
    float v = (c < FIN) ? feats[r * FIN + c] : 0.f;
    splitw(v, oh[idx], ol[idx]);
}
__global__ void k_splitWc(const float* __restrict__ Wg, const float* __restrict__ Whh,
                          __half* __restrict__ oh) {
    int idx = blockIdx.x * blockDim.x + threadIdx.x;
    if (idx >= 10000 * 2048) return;
    int r = idx >> 11, c = idx & 2047;
    float v = 0.f;
    if (c < 2000) v = (r < 4000) ? Wg[(size_t)r * 2000 + c] : Whh[(size_t)(r - 4000) * 2000 + c];
    oh[idx] = __float2half_rn(v);
}

// ---------------- CSR build ----------------
__global__ void k_zero_int(int* p, int n) {
    int i = blockIdx.x * blockDim.x + threadIdx.x;
    if (i < n) p[i] = 0;
}
__global__ void k_count(const int* __restrict__ dst, int* cnt) {
    int i = blockIdx.x * blockDim.x + threadIdx.x;
    if (i < EE) atomicAdd(&cnt[dst[i]], 1);
}
__global__ void k_scan(const int* __restrict__ cnt, int* __restrict__ off) {
    int tid = threadIdx.x;
    int a = (2 * tid < NN) ? cnt[2 * tid] : 0;
    int b = (2 * tid + 1 < NN) ? cnt[2 * tid + 1] : 0;
    int ts = a + b;
    int lane = tid & 31, wid = tid >> 5;
    int v = ts;
#pragma unroll
    for (int d = 1; d < 32; d <<= 1) {
        int u = __shfl_up_sync(0xffffffffu, v, d);
        if (lane >= d) v += u;
    }
    __shared__ int ws[32];
    if (lane == 31) ws[wid] = v;
    __syncthreads();
    if (wid == 0) {
        int w = ws[lane];
#pragma unroll
        for (int d = 1; d < 32; d <<= 1) {
            int u = __shfl_up_sync(0xffffffffu, w, d);
            if (lane >= d) w += u;
        }
        ws[lane] = w;
    }
    __syncthreads();
    int incl = v + (wid > 0 ? ws[wid - 1] : 0);
    int excl = incl - ts;
    if (2 * tid <= NN) off[2 * tid] = excl;
    if (2 * tid + 1 <= NN) off[2 * tid + 1] = excl + a;
}
__global__ void k_fill(const int* __restrict__ src, const int* __restrict__ dst,
                       const int* __restrict__ et, const int* __restrict__ off,
                       int* cnt, int* __restrict__ csr) {
    int i = blockIdx.x * blockDim.x + threadIdx.x;
    if (i < EE) {
        int d = dst[i];
        int p = off[d] + atomicAdd(&cnt[d], 1);
        csr[p] = src[i] * 2 + et[i];
    }
}
__global__ void k_boff(const int* __restrict__ batch, int* boff) {
    int i = blockIdx.x * blockDim.x + threadIdx.x;
    if (i >= NN) return;
    int b = batch[i];
    if (i == 0) {
        for (int x = 0; x <= b; x++) boff[x] = 0;
    } else {
        int pb = batch[i - 1];
        if (pb != b) for (int x = pb + 1; x <= b; x++) boff[x] = i;
    }
    if (i == NN - 1) {
        for (int x = b + 1; x <= BB; x++) boff[x] = NN;
    }
}

// ---------------- GGNN pieces ----------------
__global__ void k_hinit(const float* __restrict__ feats, float* __restrict__ h) {
    int i = blockIdx.x * blockDim.x + threadIdx.x;
    if (i >= NN * HH) return;
    int r = i / HH, c = i % HH;
    h[i] = (c < FIN) ? feats[r * FIN + c] : 0.f;
}
__global__ void k_agg(const float* __restrict__ te, const int* __restrict__ off,
                      const int* __restrict__ csr, __half* __restrict__ ah,
                      __half* __restrict__ al) {
    int d = blockIdx.x;
    int j = blockIdx.y * 256 + threadIdx.x;
    size_t o = (size_t)d * 2048 + j;
    if (j >= 2000) { ah[o] = __half(0.f); al[o] = __half(0.f); return; }
    int s0 = off[d], s1 = off[d + 1];
    float acc = 0.f;
    for (int p = s0; p < s1; p++) {
        int v = csr[p];
        int sn = v >> 1, e = v & 1;
        acc += te[(size_t)sn * 4000 + e * 2000 + j];
    }
    splitw(acc, ah[o], al[o]);
}
__global__ void k_cell(const float* __restrict__ gi, const float* __restrict__ gh,
                       float* __restrict__ h, __half* __restrict__ hh,
                       __half* __restrict__ hl) {
    int i = blockIdx.x * blockDim.x + threadIdx.x;
    if (i >= NN * HH) return;
    int r = i / HH, c = i % HH;
    size_t gI = (size_t)r * 6000 + c;
    float rr = sigm(gi[gI] + gh[gI]);
    float zz = sigm(gi[gI + 2000] + gh[gI + 2000]);
    float nn = tanhf(gi[gI + 4000] + rr * gh[gI + 4000]);
    float hv = (1.f - zz) * nn + zz * h[i];
    h[i] = hv;
    size_t o = (size_t)r * 2048 + c;
    splitw(hv, hh[o], hl[o]);
}
__global__ void k_segmax(const float* __restrict__ h, const int* __restrict__ boff,
                         __half* __restrict__ ch, __half* __restrict__ cl) {
    int b = blockIdx.y;
    int j = blockIdx.x * 256 + threadIdx.x;
    if (j >= HH) return;
    int s = boff[b], e = boff[b + 1];
    float m = -INFINITY;
    for (int i = s; i < e; i++) m = fmaxf(m, h[(size_t)i * HH + j]);
    splitw(m, ch[b * 3200 + j], cl[b * 3200 + j]);
}

// ---------------- token branch ----------------
__global__ void k_embed(const float* __restrict__ ew, const int* __restrict__ tokens,
                        __half* __restrict__ xh, __half* __restrict__ xl) {
    int tb = blockIdx.x;
    int t = tb / BB, b = tb % BB;
    int tok = tokens[b * LL + t];
    size_t ro = (size_t)tb * 448;
    for (int j = threadIdx.x; j < 448; j += blockDim.x) {
        float v = (j < FIN) ? ew[(size_t)tok * FIN + j] : 0.f;
        splitw(v, xh[ro + j], xl[ro + j]);
    }
}
__global__ void k_zpad(__half* __restrict__ xh, __half* __restrict__ xl) {
    int idx = blockIdx.x * blockDim.x + threadIdx.x;
    if (idx >= 4096 * 48) return;
    int r = idx / 48, c = 400 + idx % 48;
    xh[(size_t)r * 448 + c] = __half(0.f);
    xl[(size_t)r * 448 + c] = __half(0.f);
}
__global__ void k_transpose_whh(const float* __restrict__ W, __half* __restrict__ WT) {
    int i = blockIdx.x * blockDim.x + threadIdx.x;
    if (i >= 6 * 600 * 200) return;
    int ld = i / (600 * 200);
    int rem = i % (600 * 200);
    int j = rem / 200, k = rem % 200;
    WT[ld * 120000 + k * 600 + j] = __float2half_rn(W[i]);
}

__global__ __launch_bounds__(256) void k_gruscan(
    const float* __restrict__ giAll,
    const __half* __restrict__ WTl,
    const float* __restrict__ bhhl,
    __half* __restrict__ yh, __half* __restrict__ yl,
    __half* __restrict__ ch, __half* __restrict__ cl,
    int layer)
{
    int cid = blockIdx.x;
    int dir = cid & 1;
    int b   = cid >> 1;
    const __half* W = WTl + dir * 120000;
    const float* bhh = bhhl + dir * 600;

    __shared__ float sh_h[200];
    __shared__ float sh_gi[600];
    __shared__ float red[8][3][200];

    int tid = threadIdx.x;
    int ks = tid >> 5;
    int jg = tid & 31;

    for (int i = tid; i < 200; i += 256) sh_h[i] = 0.f;

    float rg[3];
    {
        int t0 = dir ? (LL - 1) : 0;
        const float* g0 = giAll + ((size_t)(t0 * BB + b)) * 1200 + dir * 600;
#pragma unroll
        for (int q = 0; q < 3; q++) {
            int i = tid + q * 256;
            rg[q] = (i < 600) ? g0[i] : 0.f;
        }
    }
    __syncthreads();

    for (int s = 0; s < LL; s++) {
#pragma unroll
        for (int q = 0; q < 3; q++) {
            int i = tid + q * 256;
            if (i < 600) sh_gi[i] = rg[q];
        }
        __syncthreads();

        if (s + 1 < LL) {
            int tn = dir ? (LL - 2 - s) : (s + 1);
            const float* gn = giAll + ((size_t)(tn * BB + b)) * 1200 + dir * 600;
#pragma unroll
            for (int q = 0; q < 3; q++) {
                int i = tid + q * 256;
                rg[q] = (i < 600) ? gn[i] : 0.f;
            }
        }

        if (jg < 25) {
            float acc[3][8];
#pragma unroll
            for (int g = 0; g < 3; g++)
#pragma unroll
                for (int jj = 0; jj < 8; jj++) acc[g][jj] = 0.f;
            int kb = ks * 25;
#pragma unroll
            for (int kk = 0; kk < 25; kk++) {
                int k = kb + kk;
                float hv = sh_h[k];
                const __half* row = W + k * 600;
#pragma unroll
                for (int g = 0; g < 3; g++) {
                    uint4 u = *reinterpret_cast<const uint4*>(row + g * 200 + jg * 8);
                    float2 f0 = __half22float2(*reinterpret_cast<__half2*>(&u.x));
                    float2 f1 = __half22float2(*reinterpret_cast<__half2*>(&u.y));
                    float2 f2 = __half22float2(*reinterpret_cast<__half2*>(&u.z));
                    float2 f3 = __half22float2(*reinterpret_cast<__half2*>(&u.w));
                    acc[g][0] += f0.x * hv; acc[g][1] += f0.y * hv;
                    acc[g][2] += f1.x * hv; acc[g][3] += f1.y * hv;
                    acc[g][4] += f2.x * hv; acc[g][5] += f2.y * hv;
                    acc[g][6] += f3.x * hv; acc[g][7] += f3.y * hv;
                }
            }
#pragma unroll
            for (int g = 0; g < 3; g++)
#pragma unroll
                for (int jj = 0; jj < 8; jj++)
                    red[ks][g][jg * 8 + jj] = acc[g][jj];
        }
        __syncthreads();

        if (tid < 200) {
            int j = tid;
            int t = dir ? (LL - 1 - s) : s;
            float gr = 0.f, gz = 0.f, gn2 = 0.f;
#pragma unroll
            for (int ki = 0; ki < 8; ki++) {
                gr += red[ki][0][j];
                gz += red[ki][1][j];
                gn2 += red[ki][2][j];
            }
            gr += bhh[j]; gz += bhh[200 + j]; gn2 += bhh[400 + j];
            float rr = sigm(sh_gi[j] + gr);
            float zz = sigm(sh_gi[200 + j] + gz);
            float nn = tanhf(sh_gi[400 + j] + rr * gn2);
            float hnew = (1.f - zz) * nn + zz * sh_h[j];
            size_t yo = ((size_t)(t * BB + b)) * 448 + dir * 200 + j;
            __half hh_ = __float2half_rn(hnew);
            __half hl_ = __float2half_rn(hnew - __half2float(hh_));
            yh[yo] = hh_; yl[yo] = hl_;
            if (s == LL - 1) {
                size_t co = (size_t)b * 3200 + 2000 + (2 * layer + dir) * 200 + j;
                ch[co] = hh_; cl[co] = hl_;
            }
            sh_h[j] = hnew;
        }
        __syncthreads();
    }
}

// ---------------- final tiny head layer ----------------
__global__ void k_head2(const float* __restrict__ f2, const float* __restrict__ W,
                        const float* __restrict__ b, float* __restrict__ out) {
    int t = threadIdx.x;
    if (t >= 32) return;
    int bb = t >> 1, n = t & 1;
    float acc = 0.f;
    for (int k = 0; k < 500; k++) acc += f2[bb * 500 + k] * W[n * 500 + k];
    out[bb * 2 + n] = fmaxf(acc + b[n], 0.f);
}

// ---------------- host side ----------------
#define SYMP(p, s) do { void* _q = nullptr; cudaGetSymbolAddress(&_q, s); p = (decltype(p))_q; } while (0)

static void tcg(cudaStream_t st, const __half* Ah, const __half* Al, int ldA,
                const __half* Bh, int ldB,
                const float* bias, float* C, int ldc, int M, int N, int K, int act) {
    dim3 g((N + 63) / 64, (M + 127) / 128);
    hgemm<<<g, 256, SMEM_DYN, st>>>(Ah, Al, ldA, Bh, ldB, bias, C, ldc, M, N, K, act);
}
static void tcg1(cudaStream_t st, const __half* Ah, int ldA,
                 const __half* Bh, int ldB,
                 const float* bias, float* C, int ldc, int M, int N, int K, int act) {
    dim3 g((N + 63) / 64, (M + 127) / 128);
    hgemm1<<<g, 256, SMEM_DYN1, st>>>(Ah, ldA, Bh, ldB, bias, C, ldc, M, N, K, act);
}

extern "C" void kernel_launch(void* const* d_in, const int* in_sizes, int n_in,
                              void* d_out, int out_size) {
    const float* feats   = (const float*)d_in[0];
    const int*   tokens  = (const int*)d_in[1];
    const int*   src     = (const int*)d_in[2];
    const int*   dst     = (const int*)d_in[3];
    const int*   etype   = (const int*)d_in[4];
    const int*   batch   = (const int*)d_in[5];
    const float* embed_w = (const float*)d_in[6];
    const float* ggnn_W  = (const float*)d_in[7];
    const float* ggnn_b  = (const float*)d_in[8];
    const float* Wih     = (const float*)d_in[9];
    const float* Whh     = (const float*)d_in[10];
    const float* bih     = (const float*)d_in[11];
    const float* bhh     = (const float*)d_in[12];
    const float* gWih    = (const float*)d_in[13];
    const float* gWhh    = (const float*)d_in[14];
    const float* gbih    = (const float*)d_in[15];
    const float* gbhh    = (const float*)d_in[16];
    const float* l1W = (const float*)d_in[17]; const float* l1b = (const float*)d_in[18];
    const float* l11W = (const float*)d_in[19]; const float* l11b = (const float*)d_in[20];
    const float* l2W = (const float*)d_in[21]; const float* l2b = (const float*)d_in[22];
    float* out = (float*)d_out;

    static bool sinit = false;
    static cudaStream_t s1, s2;
    static cudaEvent_t eF, eJ, eH[3], eG[3];
    if (!sinit) {
        cudaFuncSetAttribute(hgemm, cudaFuncAttributeMaxDynamicSharedMemorySize, SMEM_DYN);
        cudaFuncSetAttribute(hgemm1, cudaFuncAttributeMaxDynamicSharedMemorySize, SMEM_DYN1);
        cudaStreamCreateWithFlags(&s1, cudaStreamNonBlocking);
        cudaStreamCreateWithFlags(&s2, cudaStreamNonBlocking);
        cudaEventCreateWithFlags(&eF, cudaEventDisableTiming);
        cudaEventCreateWithFlags(&eJ, cudaEventDisableTiming);
        for (int i = 0; i < 3; i++) {
            cudaEventCreateWithFlags(&eH[i], cudaEventDisableTiming);
            cudaEventCreateWithFlags(&eG[i], cudaEventDisableTiming);
        }
        sinit = true;
    }

    float *p_h, *p_te, *p_gh, *p_gi, *p_gt, *p_f1, *p_f2;
    int *p_off, *p_cnt, *p_csr, *p_boff;
    __half *hh, *hl, *ah, *al, *Wch, *Wihh, *gWh, *p_WTh;
    __half *l1h, *l11h, *xh, *xl, *x2h, *x2l, *ch, *cl, *f1h, *f1l;
    SYMP(p_h, g_h); SYMP(p_te, g_te); SYMP(p_gh, g_gh); SYMP(p_gi, g_gi);
    SYMP(p_off, g_off); SYMP(p_cnt, g_cnt); SYMP(p_csr, g_csr); SYMP(p_boff, g_boff);
    SYMP(p_gt, g_gt); SYMP(p_f1, g_f1); SYMP(p_f2, g_f2);
    SYMP(hh, g_hh); SYMP(hl, g_hl); SYMP(ah, g_ah); SYMP(al, g_al);
    SYMP(Wch, g_Wch); SYMP(Wihh, g_Wihh); SYMP(gWh, g_gWh); SYMP(p_WTh, g_WTh);
    SYMP(l1h, g_l1h); SYMP(l11h, g_l11h);
    SYMP(xh, g_xh); SYMP(xl, g_xl); SYMP(x2h, g_x2h); SYMP(x2l, g_x2l);
    SYMP(ch, g_ch); SYMP(cl, g_cl); SYMP(f1h, g_f1h); SYMP(f1l, g_f1l);

    cudaEventRecord(eF, 0);

    // ---- prep ----
    k_splitfeats<<<(2000 * 2048 + 255) / 256, 256>>>(feats, hh, hl);
    k_splitWc<<<(10000 * 2048 + 255) / 256, 256>>>(ggnn_W, Whh, Wch);
    k_hinit<<<(NN * HH + 255) / 256, 256>>>(feats, p_h);
    cudaEventRecord(eH[0], 0);

    // CSR + batch offsets
    k_zero_int<<<(NN + 255) / 256, 256>>>(p_cnt, NN);
    k_count<<<(EE + 255) / 256, 256>>>(dst, p_cnt);
    k_scan<<<1, 1024>>>(p_cnt, p_off);
    k_zero_int<<<(NN + 255) / 256, 256>>>(p_cnt, NN);
    k_fill<<<(EE + 255) / 256, 256>>>(src, dst, etype, p_off, p_cnt, p_csr);
    k_boff<<<(NN + 255) / 256, 256>>>(batch, p_boff);
    k_tohalf<<<(6000 * 2048 + 255) / 256, 256>>>(Wih, Wihh, 6000, 2000, 2048);
    k_tohalf<<<(1000 * 3200 + 255) / 256, 256>>>(l1W, l1h, 1000, 3200, 3200);
    k_tohalf<<<(500 * 1024 + 255) / 256, 256>>>(l11W, l11h, 500, 1000, 1024);

    // ---- GGNN steps: gh GEMM on s2 overlaps etype->agg->gi chain ----
    for (int step = 0; step < 3; step++) {
        int Kh = (step == 0) ? 128 : 2048;
        cudaStreamWaitEvent(s2, eH[step], 0);
        tcg1(s2, hh, 2048, Wch + (size_t)4000 * 2048, 2048, bhh, p_gh, 6000, NN, 6000, Kh, 0);
        cudaEventRecord(eG[step], s2);

        tcg1(0, hh, 2048, Wch, 2048, ggnn_b, p_te, 4000, NN, 4000, Kh, 0);
        k_agg<<<dim3(NN, 8), 256>>>(p_te, p_off, p_csr, ah, al);
        tcg1(0, ah, 2048, Wihh, 2048, bih, p_gi, 6000, NN, 6000, 2048, 0);
        cudaStreamWaitEvent(0, eG[step], 0);
        k_cell<<<(NN * HH + 255) / 256, 256>>>(p_gi, p_gh, p_h, hh, hl);
        if (step < 2) cudaEventRecord(eH[step + 1], 0);
    }
    k_segmax<<<dim3(8, BB), 256>>>(p_h, p_boff, ch, cl);

    // ---- token branch on s1 ----
    cudaStreamWaitEvent(s1, eF, 0);
    k_embed<<<LL * BB, 128, 0, s1>>>(embed_w, tokens, xh, xl);
    k_zpad<<<(4096 * 48 + 255) / 256, 256, 0, s1>>>(x2h, x2l);
    k_transpose_whh<<<(6 * 600 * 200 + 255) / 256, 256, 0, s1>>>(gWhh, p_WTh);
    k_tohalf<<<(3600 * 448 + 255) / 256, 256, 0, s1>>>(gWih, gWh, 3600, 400, 448);

    __half* inh = xh;  __half* inl = xl;
    __half* outh = x2h; __half* outl = x2l;
    for (int l = 0; l < 3; l++) {
        tcg(s1, inh, inl, 448, gWh + (size_t)l * 1200 * 448, 448,
            gbih + l * 1200, p_gt, 1200, LL * BB, 1200, 448, 0);
        k_gruscan<<<32, 256, 0, s1>>>(p_gt, p_WTh + l * 240000, gbhh + l * 1200,
                                      outh, outl, ch, cl, l);
        __half* t1 = inh; inh = outh; outh = t1;
        __half* t2 = inl; inl = outl; outl = t2;
    }
    cudaEventRecord(eJ, s1);
    cudaStreamWaitEvent(0, eJ, 0);

    // ---- head ----
    tcg(0, ch, cl, 3200, l1h, 3200, l1b, p_f1, 1000, BB, 1000, 3200, 1);
    k_split<<<(16 * 1024 + 255) / 256, 256>>>(p_f1, f1h, f1l, BB, 1000, 1024);
    tcg(0, f1h, f1l, 1024, l11h, 1024, l11b, p_f2, 500, BB, 500, 1024, 1);
    k_head2<<<1, 32>>>(p_f2, l2W, l2b, out);

    (void)in_sizes; (void)n_in; (void)out_size;
}